// round 7
// baseline (speedup 1.0000x reference)
#include <cuda_runtime.h>
#include <cstdint>

// ---------------------------------------------------------------------------
// SubsetOperator: output = one-hot(top_k(scores)) in fp32.
// Reference forward reduces exactly to this (non-selected lanes exactly 0.0f,
// selected 1.0f within ~2 ulp; top_k(khot)==top_k(scores), boundary margin
// ~6.5e-3 >> all perturbations).
//
// R5: two kernels only.
//   kA: fused zero-fill + per-warp segment max + per-block max  [HBM pass]
//   kB: every block redundantly computes T = exact k-th largest block-max
//       (O(512^2) smem ranking), scans its 64-segment slice for candidates
//       >= T, then the last-done block (128 arrivals) ranks candidates
//       O(C^2) and writes 1.0f at the top-k indices.
// ---------------------------------------------------------------------------

#define SEG_ELEMS 2048
#define SEG_F4    (SEG_ELEMS / 4)
#define MAX_SEGS  8192
#define MAX_BLKA  512
#define CAND_CAP  (1 << 20)
#define SMEM_KEYS 4096
#define MAXK      1024
#define TPB_A     512
#define WARPS_A   (TPB_A / 32)
#define TPB_B     256
#define GRID_B    128

__device__ unsigned int       g_seg_max[MAX_SEGS];
__device__ unsigned int       g_blk_max[MAX_BLKA];
__device__ unsigned long long g_cand[CAND_CAP];
__device__ int                g_cand_count;   // zero-init; reset each replay
__device__ unsigned int      g_done_b;        // zero-init; reset each replay

// monotone mapping: fp32 total order -> uint32 order
__device__ __forceinline__ unsigned int fmono(float x) {
    unsigned int b = __float_as_uint(x);
    return b ^ ((unsigned int)((int)b >> 31) | 0x80000000u);
}

// ---------------------------------------------------------------------------
// kA: fused zero-fill + per-warp segment max + per-block max. Pure pass.
// ---------------------------------------------------------------------------
__global__ void kA(const float* __restrict__ scores, float* __restrict__ out,
                   int n, int nSeg) {
    __shared__ unsigned int wmax[WARPS_A];
    int warp = threadIdx.x >> 5;
    int lane = threadIdx.x & 31;
    int seg  = blockIdx.x * WARPS_A + warp;

    unsigned int m = 0u;
    if (seg < nSeg) {
        const float4* s4 = (const float4*)scores;
        float4*       o4 = (float4*)out;
        int base4 = seg * SEG_F4;
        float4 z = make_float4(0.f, 0.f, 0.f, 0.f);

#pragma unroll
        for (int j = 0; j < SEG_F4 / 32; ++j) {        // 16 iters per lane
            int idx4 = base4 + j * 32 + lane;
            int e0   = idx4 * 4;
            if (e0 + 3 < n) {
                float4 v = s4[idx4];
                o4[idx4] = z;
                unsigned int u0 = fmono(v.x), u1 = fmono(v.y);
                unsigned int u2 = fmono(v.z), u3 = fmono(v.w);
                unsigned int a = u0 > u1 ? u0 : u1;
                unsigned int b = u2 > u3 ? u2 : u3;
                unsigned int c = a > b ? a : b;
                if (c > m) m = c;
            } else {                                    // generic tail
                for (int e = 0; e < 4; ++e) {
                    int i = e0 + e;
                    if (i < n) {
                        unsigned int u = fmono(scores[i]);
                        if (u > m) m = u;
                        out[i] = 0.f;
                    }
                }
            }
        }
#pragma unroll
        for (int off = 16; off > 0; off >>= 1) {
            unsigned int o = __shfl_xor_sync(0xFFFFFFFFu, m, off);
            if (o > m) m = o;
        }
        if (lane == 0) g_seg_max[seg] = m;
    }
    if (lane == 0) wmax[warp] = m;
    __syncthreads();
    if (warp == 0) {
        unsigned int v = (lane < WARPS_A) ? wmax[lane] : 0u;
#pragma unroll
        for (int off = 8; off > 0; off >>= 1) {
            unsigned int o = __shfl_xor_sync(0xFFFFFFFFu, v, off);
            if (o > v) v = o;
        }
        if (lane == 0) g_blk_max[blockIdx.x] = v;
    }
}

// ---------------------------------------------------------------------------
// kB: threshold (redundant per block) + candidate collection + final ranking
// in the last-done block. Grid = GRID_B blocks of TPB_B threads.
// ---------------------------------------------------------------------------
__global__ void kB(const float* __restrict__ scores, float* __restrict__ out,
                   const int* kptr, int n, int nSeg, int nBlkA) {
    __shared__ union {
        unsigned int       svals[MAX_SEGS];    // phase 1: maxima (<=32KB)
        unsigned long long skeys[SMEM_KEYS];   // phase 3: candidate keys
    } shu;
    __shared__ unsigned int s_T;
    __shared__ int  s_flist[MAX_SEGS / GRID_B + 1];
    __shared__ int  s_fcnt;
    __shared__ unsigned int s_islast;

    int tid = threadIdx.x;

    // ---- phase 1: T = exact k-th largest maximum (redundant per block) ----
    int k = kptr ? *kptr : 32;
    if (k < 1) k = 1;
    if (k > MAXK) k = MAXK;

    // source: 512 block-maxima normally; all segment maxima if k > nBlkA
    const unsigned int* src = (k <= nBlkA) ? g_blk_max : g_seg_max;
    int M = (k <= nBlkA) ? nBlkA : nSeg;
    if (k > M) k = M;                       // degenerate guard

    if (tid == 0) { s_fcnt = 0; s_T = 0u; }
    for (int j = tid; j < M; j += TPB_B) shu.svals[j] = src[j];
    __syncthreads();

    for (int j = tid; j < M; j += TPB_B) {
        unsigned int v = shu.svals[j];
        int r = 0, eq = 0;
        for (int i = 0; i < M; ++i) {
            unsigned int u = shu.svals[i];
            r  += (u > v);
            eq += (u == v);
        }
        if (r < k && r + eq >= k) s_T = v;  // the k-th order statistic value
    }
    __syncthreads();
    unsigned int T = s_T;

    // ---- phase 2: scan owned segment slice for candidates >= T ----
    int segPerBlk = (nSeg + GRID_B - 1) / GRID_B;
    int s0 = blockIdx.x * segPerBlk;
    int s1 = s0 + segPerBlk; if (s1 > nSeg) s1 = nSeg;

    for (int j = s0 + tid; j < s1; j += TPB_B) {        // parallel flag loads
        if (g_seg_max[j] >= T) {
            int p = atomicAdd(&s_fcnt, 1);
            s_flist[p] = j;
        }
    }
    __syncthreads();
    int F = s_fcnt;

    const float4* s4 = (const float4*)scores;
    for (int f = 0; f < F; ++f) {
        int base4 = s_flist[f] * SEG_F4;
        for (int t = tid; t < SEG_F4; t += TPB_B) {
            int idx4 = base4 + t;
            int e0   = idx4 * 4;
            if (e0 + 3 < n) {
                float4 v = s4[idx4];
                unsigned int u[4] = {fmono(v.x), fmono(v.y), fmono(v.z), fmono(v.w)};
#pragma unroll
                for (int e = 0; e < 4; ++e) {
                    if (u[e] >= T) {
                        int p = atomicAdd(&g_cand_count, 1);
                        if (p < CAND_CAP)
                            g_cand[p] = ((unsigned long long)u[e] << 32) |
                                        (unsigned int)(0xFFFFFFFFu - (unsigned int)(e0 + e));
                    }
                }
            } else {
                for (int e = 0; e < 4; ++e) {
                    int i = e0 + e;
                    if (i < n) {
                        unsigned int u = fmono(scores[i]);
                        if (u >= T) {
                            int p = atomicAdd(&g_cand_count, 1);
                            if (p < CAND_CAP)
                                g_cand[p] = ((unsigned long long)u << 32) |
                                            (unsigned int)(0xFFFFFFFFu - (unsigned int)i);
                        }
                    }
                }
            }
        }
    }

    // ---- last-block-done (128 arrivals) ----
    __threadfence();
    __syncthreads();
    if (tid == 0)
        s_islast = (atomicAdd(&g_done_b, 1u) == (unsigned int)(GRID_B - 1));
    __syncthreads();
    if (!s_islast) return;
    __threadfence();

    // ---- phase 3: rank candidates, write 1.0f at top-k ----
    int C = g_cand_count;
    if (C > CAND_CAP) C = CAND_CAP;

    if (C <= SMEM_KEYS) {
        for (int j = tid; j < C; j += TPB_B) shu.skeys[j] = g_cand[j];
        __syncthreads();
        for (int j = tid; j < C; j += TPB_B) {
            unsigned long long kj = shu.skeys[j];
            int rank = 0;
            for (int i = 0; i < C; ++i) rank += (shu.skeys[i] > kj);
            if (rank < k)
                out[0xFFFFFFFFu - (unsigned int)(kj & 0xFFFFFFFFu)] = 1.0f;
        }
    } else {   // fallback, never hit for this data
        for (int j = tid; j < C; j += TPB_B) {
            unsigned long long kj = g_cand[j];
            int rank = 0;
            for (int i = 0; i < C; ++i) rank += (g_cand[i] > kj);
            if (rank < k)
                out[0xFFFFFFFFu - (unsigned int)(kj & 0xFFFFFFFFu)] = 1.0f;
        }
    }
    __syncthreads();
    if (tid == 0) {                 // reset for next graph replay
        g_cand_count = 0;
        g_done_b = 0;
    }
}

// ---------------------------------------------------------------------------
extern "C" void kernel_launch(void* const* d_in, const int* in_sizes, int n_in,
                              void* d_out, int out_size) {
    const float* scores = (const float*)d_in[0];
    int n = in_sizes[0];
    const int* kptr = nullptr;
    for (int i = 0; i < n_in; ++i) {
        if (in_sizes[i] == 1) {
            kptr = (const int*)d_in[i];
        } else {
            scores = (const float*)d_in[i];
            n = in_sizes[i];
        }
    }
    float* out = (float*)d_out;

    int nSeg = (n + SEG_ELEMS - 1) / SEG_ELEMS;        // 8192 for N = 16,777,216
    if (nSeg > MAX_SEGS) nSeg = MAX_SEGS;
    int nBlkA = (nSeg + WARPS_A - 1) / WARPS_A;        // 512
    if (nBlkA > MAX_BLKA) nBlkA = MAX_BLKA;

    kA<<<nBlkA, TPB_A>>>(scores, out, n, nSeg);
    kB<<<GRID_B, TPB_B>>>(scores, out, kptr, n, nSeg, nBlkA);
}

// round 8
// speedup vs baseline: 1.0471x; 1.0471x over previous
#include <cuda_runtime.h>
#include <cstdint>

// ---------------------------------------------------------------------------
// SubsetOperator: output = one-hot(top_k(scores)) in fp32.
// Reference forward reduces exactly to this (non-selected lanes exactly 0.0f,
// selected 1.0f within ~2 ulp; top_k(khot)==top_k(scores), boundary margin
// ~6.5e-3 >> all perturbations).
//
// R7: three kernels.
//   kA : fused zero-fill + per-warp segment max + per-block max  [HBM pass]
//   kS : ONE block ranks the 512 block-maxima once -> T = exact k-th largest
//        (valid threshold: >=k blocks each contain an element >= T)
//   kCD: 32 blocks scan only segments with segmax >= T (~32 segs, L2-hot),
//        collect candidates; last-done block (32 arrivals) ranks C~35
//        candidates O(C^2) and writes 1.0f at the top-k indices.
// ---------------------------------------------------------------------------

#define SEG_ELEMS 2048
#define SEG_F4    (SEG_ELEMS / 4)
#define MAX_SEGS  8192
#define MAX_BLKA  512
#define CAND_CAP  (1 << 20)
#define SMEM_KEYS 4096
#define MAXK      1024
#define TPB_A     512
#define WARPS_A   (TPB_A / 32)
#define TPB_S     1024
#define GRID_C    32
#define TPB_C     256

__device__ unsigned int       g_seg_max[MAX_SEGS];
__device__ unsigned int       g_blk_max[MAX_BLKA];
__device__ unsigned long long g_cand[CAND_CAP];
__device__ int                g_cand_count;   // zero-init; reset each replay
__device__ unsigned int      g_done;          // zero-init; reset each replay
__device__ unsigned int      g_thresh;
__device__ int               g_k;

// monotone mapping: fp32 total order -> uint32 order
__device__ __forceinline__ unsigned int fmono(float x) {
    unsigned int b = __float_as_uint(x);
    return b ^ ((unsigned int)((int)b >> 31) | 0x80000000u);
}

// ---------------------------------------------------------------------------
// kA: fused zero-fill + per-warp segment max + per-block max. Pure pass.
// ---------------------------------------------------------------------------
__global__ void kA(const float* __restrict__ scores, float* __restrict__ out,
                   int n, int nSeg) {
    __shared__ unsigned int wmax[WARPS_A];
    int warp = threadIdx.x >> 5;
    int lane = threadIdx.x & 31;
    int seg  = blockIdx.x * WARPS_A + warp;

    unsigned int m = 0u;
    if (seg < nSeg) {
        const float4* s4 = (const float4*)scores;
        float4*       o4 = (float4*)out;
        int base4 = seg * SEG_F4;
        float4 z = make_float4(0.f, 0.f, 0.f, 0.f);

#pragma unroll
        for (int j = 0; j < SEG_F4 / 32; ++j) {        // 16 iters per lane
            int idx4 = base4 + j * 32 + lane;
            int e0   = idx4 * 4;
            if (e0 + 3 < n) {
                float4 v = s4[idx4];
                o4[idx4] = z;
                unsigned int u0 = fmono(v.x), u1 = fmono(v.y);
                unsigned int u2 = fmono(v.z), u3 = fmono(v.w);
                unsigned int a = u0 > u1 ? u0 : u1;
                unsigned int b = u2 > u3 ? u2 : u3;
                unsigned int c = a > b ? a : b;
                if (c > m) m = c;
            } else {                                    // generic tail
                for (int e = 0; e < 4; ++e) {
                    int i = e0 + e;
                    if (i < n) {
                        unsigned int u = fmono(scores[i]);
                        if (u > m) m = u;
                        out[i] = 0.f;
                    }
                }
            }
        }
#pragma unroll
        for (int off = 16; off > 0; off >>= 1) {
            unsigned int o = __shfl_xor_sync(0xFFFFFFFFu, m, off);
            if (o > m) m = o;
        }
        if (lane == 0) g_seg_max[seg] = m;
    }
    if (lane == 0) wmax[warp] = m;
    __syncthreads();
    if (warp == 0) {
        unsigned int v = (lane < WARPS_A) ? wmax[lane] : 0u;
#pragma unroll
        for (int off = 8; off > 0; off >>= 1) {
            unsigned int o = __shfl_xor_sync(0xFFFFFFFFu, v, off);
            if (o > v) v = o;
        }
        if (lane == 0) g_blk_max[blockIdx.x] = v;
    }
}

// ---------------------------------------------------------------------------
// kS: one block, one-shot exact k-th order statistic over the block maxima.
// Normal path M = nBlkA = 512 (one value per thread, 512 inner iterations,
// computed ONCE on the whole chip). Fallback to segment maxima if k > nBlkA.
// ---------------------------------------------------------------------------
__global__ void kS(const int* kptr, int nSeg, int nBlkA) {
    __shared__ unsigned int svals[MAX_SEGS];   // 32 KB worst case
    int tid = threadIdx.x;

    int k = kptr ? *kptr : 32;
    if (k < 1) k = 1;
    if (k > MAXK) k = MAXK;

    const unsigned int* src = (k <= nBlkA) ? g_blk_max : g_seg_max;
    int M = (k <= nBlkA) ? nBlkA : nSeg;
    if (k > M) k = M;

    for (int j = tid; j < M; j += TPB_S) svals[j] = src[j];
    __syncthreads();

    for (int j = tid; j < M; j += TPB_S) {
        unsigned int v = svals[j];
        int r = 0, eq = 0;
        for (int i = 0; i < M; ++i) {
            unsigned int u = svals[i];
            r  += (u > v);
            eq += (u == v);
        }
        if (r < k && r + eq >= k) g_thresh = v;   // unique: k-th largest value
    }
    if (tid == 0) g_k = k;
}

// ---------------------------------------------------------------------------
// kCD: collect candidates >= T from flagged segments (each block owns a
// nSeg/GRID_C slice), then the last-done block ranks them and writes 1.0f.
// Key = (u << 32) | ~idx  -> larger key = larger value, ties -> lower index
// (matches lax.top_k ordering). Order-independent, so deterministic.
// ---------------------------------------------------------------------------
__global__ void kCD(const float* __restrict__ scores, float* __restrict__ out,
                    int n, int nSeg) {
    __shared__ union {
        int                flist[MAX_SEGS / GRID_C + 1];
        unsigned long long skeys[SMEM_KEYS];
    } sh;
    __shared__ int s_fcnt;
    __shared__ unsigned int s_islast;

    int tid = threadIdx.x;
    unsigned int T = g_thresh;

    // ---- flag owned segments (parallel loads of g_seg_max) ----
    if (tid == 0) s_fcnt = 0;
    __syncthreads();
    int segPerBlk = (nSeg + GRID_C - 1) / GRID_C;
    int s0 = blockIdx.x * segPerBlk;
    int s1 = s0 + segPerBlk; if (s1 > nSeg) s1 = nSeg;
    for (int j = s0 + tid; j < s1; j += TPB_C) {
        if (g_seg_max[j] >= T) {
            int p = atomicAdd(&s_fcnt, 1);
            sh.flist[p] = j;
        }
    }
    __syncthreads();
    int F = s_fcnt;

    // ---- scan flagged segments, append candidates ----
    const float4* s4 = (const float4*)scores;
    for (int f = 0; f < F; ++f) {
        int base4 = sh.flist[f] * SEG_F4;
        for (int t = tid; t < SEG_F4; t += TPB_C) {
            int idx4 = base4 + t;
            int e0   = idx4 * 4;
            if (e0 + 3 < n) {
                float4 v = s4[idx4];
                unsigned int u[4] = {fmono(v.x), fmono(v.y), fmono(v.z), fmono(v.w)};
#pragma unroll
                for (int e = 0; e < 4; ++e) {
                    if (u[e] >= T) {
                        int p = atomicAdd(&g_cand_count, 1);
                        if (p < CAND_CAP)
                            g_cand[p] = ((unsigned long long)u[e] << 32) |
                                        (unsigned int)(0xFFFFFFFFu - (unsigned int)(e0 + e));
                    }
                }
            } else {
                for (int e = 0; e < 4; ++e) {
                    int i = e0 + e;
                    if (i < n) {
                        unsigned int u = fmono(scores[i]);
                        if (u >= T) {
                            int p = atomicAdd(&g_cand_count, 1);
                            if (p < CAND_CAP)
                                g_cand[p] = ((unsigned long long)u << 32) |
                                            (unsigned int)(0xFFFFFFFFu - (unsigned int)i);
                        }
                    }
                }
            }
        }
    }

    // ---- last-done protocol: only 32 arrivals ----
    __threadfence();
    __syncthreads();
    if (tid == 0)
        s_islast = (atomicAdd(&g_done, 1u) == (unsigned int)(GRID_C - 1));
    __syncthreads();
    if (!s_islast) return;
    __threadfence();

    // ---- rank candidates, write 1.0f at top-k ----
    int C = g_cand_count;
    if (C > CAND_CAP) C = CAND_CAP;
    int k = g_k;

    if (C <= SMEM_KEYS) {
        for (int j = tid; j < C; j += TPB_C) sh.skeys[j] = g_cand[j];
        __syncthreads();
        for (int j = tid; j < C; j += TPB_C) {
            unsigned long long kj = sh.skeys[j];
            int rank = 0;
            for (int i = 0; i < C; ++i) rank += (sh.skeys[i] > kj);
            if (rank < k)
                out[0xFFFFFFFFu - (unsigned int)(kj & 0xFFFFFFFFu)] = 1.0f;
        }
    } else {   // fallback, never hit for this data
        for (int j = tid; j < C; j += TPB_C) {
            unsigned long long kj = g_cand[j];
            int rank = 0;
            for (int i = 0; i < C; ++i) rank += (g_cand[i] > kj);
            if (rank < k)
                out[0xFFFFFFFFu - (unsigned int)(kj & 0xFFFFFFFFu)] = 1.0f;
        }
    }
    __syncthreads();
    if (tid == 0) {                 // reset for next graph replay
        g_cand_count = 0;
        g_done = 0;
    }
}

// ---------------------------------------------------------------------------
extern "C" void kernel_launch(void* const* d_in, const int* in_sizes, int n_in,
                              void* d_out, int out_size) {
    const float* scores = (const float*)d_in[0];
    int n = in_sizes[0];
    const int* kptr = nullptr;
    for (int i = 0; i < n_in; ++i) {
        if (in_sizes[i] == 1) {
            kptr = (const int*)d_in[i];
        } else {
            scores = (const float*)d_in[i];
            n = in_sizes[i];
        }
    }
    float* out = (float*)d_out;

    int nSeg = (n + SEG_ELEMS - 1) / SEG_ELEMS;        // 8192 for N = 16,777,216
    if (nSeg > MAX_SEGS) nSeg = MAX_SEGS;
    int nBlkA = (nSeg + WARPS_A - 1) / WARPS_A;        // 512
    if (nBlkA > MAX_BLKA) nBlkA = MAX_BLKA;

    kA<<<nBlkA, TPB_A>>>(scores, out, n, nSeg);
    kS<<<1, TPB_S>>>(kptr, nSeg, nBlkA);
    kCD<<<GRID_C, TPB_C>>>(scores, out, n, nSeg);
}

// round 10
// speedup vs baseline: 1.2329x; 1.1775x over previous
#include <cuda_runtime.h>
#include <cstdint>

// ---------------------------------------------------------------------------
// SubsetOperator: output = one-hot(top_k(scores)) in fp32.
// Reference forward reduces exactly to this (non-selected lanes exactly 0.0f,
// selected 1.0f within ~2 ulp; top_k(khot)==top_k(scores), boundary margin
// ~6.5e-3 >> all perturbations).
//
// R8: TWO kernels.
//   kA : fused zero-fill + per-256-elem sub-max + per-2048 segment max +
//        per-block max. Streaming cache hints (ldcs/stcs) to cut L2 thrash.
//   kZ : ONE block. T = exact k-th largest block-max; drill down
//        segmax -> submax -> elements (only ~40 x 256-elem sub-segments
//        scanned), O(C^2) rank of ~50 candidates, write 1.0f at top-k.
// ---------------------------------------------------------------------------

#define SEG_ELEMS   2048
#define SEG_F4      (SEG_ELEMS / 4)
#define SUB_F4      64                 // 256 elems per sub-segment
#define SUBS_PER_SEG 8
#define MAX_SEGS    8192
#define MAX_SUB     (MAX_SEGS * SUBS_PER_SEG)
#define MAX_BLKA    512
#define MAXK        1024
#define TPB_A       512
#define WARPS_A     (TPB_A / 32)
#define TPB_Z       1024
#define SEGL_CAP    1024
#define SUBL_CAP    2048
#define CKEY_CAP    2048

__device__ unsigned int g_seg_max[MAX_SEGS];
__device__ unsigned int g_sub_max[MAX_SUB];
__device__ unsigned int g_blk_max[MAX_BLKA];

// monotone mapping: fp32 total order -> uint32 order
__device__ __forceinline__ unsigned int fmono(float x) {
    unsigned int b = __float_as_uint(x);
    return b ^ ((unsigned int)((int)b >> 31) | 0x80000000u);
}

// ---------------------------------------------------------------------------
// kA: fused zero-fill + sub/seg/block maxima. Pure streaming pass.
// ---------------------------------------------------------------------------
__global__ void kA(const float* __restrict__ scores, float* __restrict__ out,
                   int n, int nSeg) {
    __shared__ unsigned int wmax[WARPS_A];
    int warp = threadIdx.x >> 5;
    int lane = threadIdx.x & 31;
    int seg  = blockIdx.x * WARPS_A + warp;

    unsigned int m = 0u;
    if (seg < nSeg) {
        const float4* s4 = (const float4*)scores;
        float4*       o4 = (float4*)out;
        int base4 = seg * SEG_F4;
        float4 z = make_float4(0.f, 0.f, 0.f, 0.f);
        unsigned int m2 = 0u;                    // running 2-iter (256-elem) max

#pragma unroll
        for (int j = 0; j < SEG_F4 / 32; ++j) {  // 16 iters, 128 elems each
            int idx4 = base4 + j * 32 + lane;
            int e0   = idx4 * 4;
            unsigned int c = 0u;
            if (e0 + 3 < n) {
                float4 v = __ldcs(s4 + idx4);    // streaming read
                __stcs(o4 + idx4, z);            // streaming zero write
                unsigned int u0 = fmono(v.x), u1 = fmono(v.y);
                unsigned int u2 = fmono(v.z), u3 = fmono(v.w);
                unsigned int a = u0 > u1 ? u0 : u1;
                unsigned int b = u2 > u3 ? u2 : u3;
                c = a > b ? a : b;
            } else {                              // generic tail
                for (int e = 0; e < 4; ++e) {
                    int i = e0 + e;
                    if (i < n) {
                        unsigned int u = fmono(scores[i]);
                        if (u > c) c = u;
                        out[i] = 0.f;
                    }
                }
            }
            if (c > m2) m2 = c;
            if (j & 1) {                          // 256-elem boundary
                unsigned int t = m2;
#pragma unroll
                for (int off = 16; off > 0; off >>= 1) {
                    unsigned int o = __shfl_xor_sync(0xFFFFFFFFu, t, off);
                    if (o > t) t = o;
                }
                if (lane == 0) g_sub_max[seg * SUBS_PER_SEG + (j >> 1)] = t;
                if (t > m) m = t;                 // butterfly: all lanes have t
                m2 = 0u;
            }
        }
        if (lane == 0) g_seg_max[seg] = m;
    }
    if (lane == 0) wmax[warp] = m;
    __syncthreads();
    if (warp == 0) {
        unsigned int v = (lane < WARPS_A) ? wmax[lane] : 0u;
#pragma unroll
        for (int off = 8; off > 0; off >>= 1) {
            unsigned int o = __shfl_xor_sync(0xFFFFFFFFu, v, off);
            if (o > v) v = o;
        }
        if (lane == 0) g_blk_max[blockIdx.x] = v;
    }
}

// ---------------------------------------------------------------------------
// kZ: single block does everything after the pass.
// ---------------------------------------------------------------------------
__global__ void kZ(const float* __restrict__ scores, float* __restrict__ out,
                   const int* kptr, int n, int nSeg, int nBlkA) {
    __shared__ union {
        unsigned int       rankvals[MAX_SEGS];   // phase 1 (<=32 KB)
        unsigned long long ckeys[CKEY_CAP];      // phases 4-5 (16 KB)
    } u;
    __shared__ int seglist[SEGL_CAP];
    __shared__ int sublist[SUBL_CAP];
    __shared__ int s_nseg, s_nsub, s_nc;
    __shared__ unsigned int s_T;
    int tid = threadIdx.x;

    // ---- phase 1: T = exact k-th largest maximum ----
    int k = kptr ? *kptr : 32;
    if (k < 1) k = 1;
    if (k > MAXK) k = MAXK;
    const unsigned int* src = (k <= nBlkA) ? g_blk_max : g_seg_max;
    int M = (k <= nBlkA) ? nBlkA : nSeg;
    if (k > M) k = M;

    if (tid == 0) { s_nseg = 0; s_nsub = 0; s_nc = 0; s_T = 0u; }
    for (int j = tid; j < M; j += TPB_Z) u.rankvals[j] = src[j];
    __syncthreads();
    for (int j = tid; j < M; j += TPB_Z) {
        unsigned int v = u.rankvals[j];
        int r = 0, eq = 0;
        for (int i = 0; i < M; ++i) {
            unsigned int w = u.rankvals[i];
            r  += (w > v);
            eq += (w == v);
        }
        if (r < k && r + eq >= k) s_T = v;       // k-th order statistic value
    }
    __syncthreads();
    unsigned int T = s_T;

    // ---- phase 2: flag segments with segmax >= T (uint4 loads) ----
    int nSeg4 = nSeg >> 2;
    const uint4* sm4 = (const uint4*)g_seg_max;
    for (int j = tid; j < nSeg4; j += TPB_Z) {
        uint4 v = sm4[j];
        int b = 4 * j;
        if (v.x >= T) { int p = atomicAdd(&s_nseg, 1); if (p < SEGL_CAP) seglist[p] = b;     }
        if (v.y >= T) { int p = atomicAdd(&s_nseg, 1); if (p < SEGL_CAP) seglist[p] = b + 1; }
        if (v.z >= T) { int p = atomicAdd(&s_nseg, 1); if (p < SEGL_CAP) seglist[p] = b + 2; }
        if (v.w >= T) { int p = atomicAdd(&s_nseg, 1); if (p < SEGL_CAP) seglist[p] = b + 3; }
    }
    for (int j = nSeg4 * 4 + tid; j < nSeg; j += TPB_Z) {
        if (g_seg_max[j] >= T) {
            int p = atomicAdd(&s_nseg, 1);
            if (p < SEGL_CAP) seglist[p] = j;
        }
    }
    __syncthreads();
    int F = s_nseg < SEGL_CAP ? s_nseg : SEGL_CAP;

    // ---- phase 3: flag sub-segments with submax >= T ----
    for (int t = tid; t < F * SUBS_PER_SEG; t += TPB_Z) {
        int sub = seglist[t >> 3] * SUBS_PER_SEG + (t & 7);
        if (g_sub_max[sub] >= T) {
            int p = atomicAdd(&s_nsub, 1);
            if (p < SUBL_CAP) sublist[p] = sub;
        }
    }
    __syncthreads();
    int F2 = s_nsub < SUBL_CAP ? s_nsub : SUBL_CAP;

    // ---- phase 4: scan flagged sub-segments, collect candidates >= T ----
    // key = (u << 32) | ~idx : larger key = larger value, ties -> lower index
    const float4* s4 = (const float4*)scores;
    int W = F2 * SUB_F4;
    for (int w = tid; w < W; w += TPB_Z) {
        int idx4 = sublist[w >> 6] * SUB_F4 + (w & 63);
        int e0   = idx4 * 4;
        if (e0 + 3 < n) {
            float4 v = s4[idx4];
            unsigned int uu[4] = {fmono(v.x), fmono(v.y), fmono(v.z), fmono(v.w)};
#pragma unroll
            for (int e = 0; e < 4; ++e) {
                if (uu[e] >= T) {
                    int p = atomicAdd(&s_nc, 1);
                    if (p < CKEY_CAP)
                        u.ckeys[p] = ((unsigned long long)uu[e] << 32) |
                                     (unsigned int)(0xFFFFFFFFu - (unsigned int)(e0 + e));
                }
            }
        } else {
            for (int e = 0; e < 4; ++e) {
                int i = e0 + e;
                if (i < n) {
                    unsigned int uu = fmono(scores[i]);
                    if (uu >= T) {
                        int p = atomicAdd(&s_nc, 1);
                        if (p < CKEY_CAP)
                            u.ckeys[p] = ((unsigned long long)uu << 32) |
                                         (unsigned int)(0xFFFFFFFFu - (unsigned int)i);
                    }
                }
            }
        }
    }
    __syncthreads();
    int C = s_nc < CKEY_CAP ? s_nc : CKEY_CAP;

    // ---- phase 5: O(C^2) rank over unique keys, write 1.0f at top-k ----
    for (int j = tid; j < C; j += TPB_Z) {
        unsigned long long kj = u.ckeys[j];
        int rank = 0;
        for (int i = 0; i < C; ++i) rank += (u.ckeys[i] > kj);
        if (rank < k)
            out[0xFFFFFFFFu - (unsigned int)(kj & 0xFFFFFFFFu)] = 1.0f;
    }
}

// ---------------------------------------------------------------------------
extern "C" void kernel_launch(void* const* d_in, const int* in_sizes, int n_in,
                              void* d_out, int out_size) {
    const float* scores = (const float*)d_in[0];
    int n = in_sizes[0];
    const int* kptr = nullptr;
    for (int i = 0; i < n_in; ++i) {
        if (in_sizes[i] == 1) {
            kptr = (const int*)d_in[i];
        } else {
            scores = (const float*)d_in[i];
            n = in_sizes[i];
        }
    }
    float* out = (float*)d_out;

    int nSeg = (n + SEG_ELEMS - 1) / SEG_ELEMS;      // 8192 for N = 16,777,216
    if (nSeg > MAX_SEGS) nSeg = MAX_SEGS;
    int nBlkA = (nSeg + WARPS_A - 1) / WARPS_A;      // 512
    if (nBlkA > MAX_BLKA) nBlkA = MAX_BLKA;

    kA<<<nBlkA, TPB_A>>>(scores, out, n, nSeg);
    kZ<<<1, TPB_Z>>>(scores, out, kptr, n, nSeg, nBlkA);
}